// round 7
// baseline (speedup 1.0000x reference)
#include <cuda_runtime.h>

// out = u2 + trilinear(u1, grid + u2), [B=2,160,160,160,3] fp32.
// smem tile padded to float4 per voxel -> conflict-free LDS.128 gathers.
// Tile sized so TWO blocks co-reside per SM.

#define Dd 160
#define Hh 160
#define Ww 160
#define HW  (Hh * Ww)
#define DHW (Dd * HW)

#define TX 10
#define TY 8
#define TZ 16
#define HALO 4
#define SX (TX + 2 * HALO)   // 18
#define SY (TY + 2 * HALO)   // 16 (power of 2)
#define SZ (TZ + 2 * HALO)   // 24
#define RS (SZ * 4)          // 96 floats per (x,y) row (padded float4 voxels)
#define NROW (SX * SY)       // 288
#define BUF (NROW * RS)      // 27648 floats = 110,592 B
#define TPB 512
#define NWARP (TPB / 32)     // 16
#define NTASK (TX * (TY / 2))// 40 warp tasks: (x, y-pair)

extern __shared__ float s[];

__global__ __launch_bounds__(TPB, 2)
void compose_vec_kernel(const float* __restrict__ w1,
                        const float* __restrict__ w2,
                        float* __restrict__ out)
{
    // blockIdx.x = xy tile (16 x-tiles inner, power of 2), .y = z chunk, .z = b
    const int xt = blockIdx.x & 15;          // 0..15
    const int yt = blockIdx.x >> 4;          // 0..19
    const int x0 = xt * TX;
    const int y0 = yt * TY;
    const int z0 = blockIdx.y * TZ;
    const int b  = blockIdx.z;

    const int t    = threadIdx.x;
    const int lane = t & 31;
    const int wrp  = t >> 5;

    const float* __restrict__ w1b = w1 + (size_t)b * (size_t)DHW * 3;

    // ---- Tile fill: LDG.128 x3 (packed) -> repack -> STS.128 x4 (padded) ----
    // One "group" = 4 consecutive-z voxels of one (x,y) row.
    {
        const int zlo   = (z0 == 0) ? 0 : z0 - HALO;
        const int zhi   = (z0 + TZ + HALO > Ww) ? Ww : z0 + TZ + HALO;
        const int szb   = zlo - (z0 - HALO);       // 0 or 4
        const bool full = (zhi - zlo) == SZ;       // 6 groups vs 5

        if (full) {
#pragma unroll 1
            for (int idx = t; idx < NROW * 6; idx += TPB) {
                const int row = idx / 6;
                const int g   = idx - row * 6;
                const int hx  = row >> 4;
                const int hy  = row & 15;
                const int cx  = x0 - HALO + hx;
                const int cy  = y0 - HALO + hy;
                if ((unsigned)cx < (unsigned)Dd && (unsigned)cy < (unsigned)Hh) {
                    const float4* src = reinterpret_cast<const float4*>(
                        w1b + ((size_t)(cx * Hh + cy) * Ww + zlo + g * 4) * 3);
                    const float4 a = src[0], c = src[1], d = src[2];
                    float4* dst = reinterpret_cast<float4*>(
                        s + (row * SZ + g * 4) * 4);
                    dst[0] = make_float4(a.x, a.y, a.z, 0.f);
                    dst[1] = make_float4(a.w, c.x, c.y, 0.f);
                    dst[2] = make_float4(c.z, c.w, d.x, 0.f);
                    dst[3] = make_float4(d.y, d.z, d.w, 0.f);
                }
            }
        } else {
#pragma unroll 1
            for (int idx = t; idx < NROW * 5; idx += TPB) {
                const int row = idx / 5;
                const int g   = idx - row * 5;
                const int hx  = row >> 4;
                const int hy  = row & 15;
                const int cx  = x0 - HALO + hx;
                const int cy  = y0 - HALO + hy;
                if ((unsigned)cx < (unsigned)Dd && (unsigned)cy < (unsigned)Hh) {
                    const float4* src = reinterpret_cast<const float4*>(
                        w1b + ((size_t)(cx * Hh + cy) * Ww + zlo + g * 4) * 3);
                    const float4 a = src[0], c = src[1], d = src[2];
                    float4* dst = reinterpret_cast<float4*>(
                        s + (row * SZ + szb + g * 4) * 4);
                    dst[0] = make_float4(a.x, a.y, a.z, 0.f);
                    dst[1] = make_float4(a.w, c.x, c.y, 0.f);
                    dst[2] = make_float4(c.z, c.w, d.x, 0.f);
                    dst[3] = make_float4(d.y, d.z, d.w, 0.f);
                }
            }
        }
    }

    // ---- Compute mapping: lane = (ysub, z16); warp task = (x, y-pair) ----
    const int ysub = lane >> 4;          // 0..1
    const int hz   = lane & 15;          // 0..15
    const int z    = z0 + hz;

    // Prefetch first task's u2 (overlaps tile LDGs in flight).
    int task = wrp;
    int nf;
    float nux, nuy, nuz;
    {
        const int x_ = x0 + (task >> 2);
        const int y_ = y0 + (task & 3) * 2 + ysub;
        nf  = (((b * Dd + x_) * Hh + y_) * Ww + z) * 3;
        nux = __ldg(w2 + nf + 0);
        nuy = __ldg(w2 + nf + 1);
        nuz = __ldg(w2 + nf + 2);
    }

    __syncthreads();

    for (; task < NTASK; task += NWARP) {
        const int x = x0 + (task >> 2);
        const int y = y0 + (task & 3) * 2 + ysub;
        const int f = nf;
        const float u2x = nux, u2y = nuy, u2z = nuz;

        if (task + NWARP < NTASK) {      // prefetch next task's u2
            const int nt = task + NWARP;
            nf  = (((b * Dd + x0 + (nt >> 2)) * Hh +
                    y0 + (nt & 3) * 2 + ysub) * Ww + z) * 3;
            nux = __ldg(w2 + nf + 0);
            nuy = __ldg(w2 + nf + 1);
            nuz = __ldg(w2 + nf + 2);
        }

        float lx = fminf(fmaxf((float)x + u2x, 0.0f), (float)(Dd - 1));
        float ly = fminf(fmaxf((float)y + u2y, 0.0f), (float)(Hh - 1));
        float lz = fminf(fmaxf((float)z + u2z, 0.0f), (float)(Ww - 1));

        const float fx = floorf(lx), fy = floorf(ly), fz = floorf(lz);
        const int ix0 = (int)fx, iy0 = (int)fy, iz0 = (int)fz;
        const float wx = lx - fx, wy = ly - fy, wz = lz - fz;
        const float wx0 = 1.0f - wx, wy0 = 1.0f - wy, wz0 = 1.0f - wz;

        const int ix1 = min(ix0 + 1, Dd - 1);
        const int iy1 = min(iy0 + 1, Hh - 1);
        const int iz1 = min(iz0 + 1, Ww - 1);

        const int sx0 = ix0 - (x0 - HALO);
        const int sy0 = iy0 - (y0 - HALO);
        const int sz0 = iz0 - (z0 - HALO);

        float ox, oy, oz;

        const bool fast = ((unsigned)sx0 <= (unsigned)(SX - 2)) &&
                          ((unsigned)sy0 <= (unsigned)(SY - 2)) &&
                          ((unsigned)sz0 <= (unsigned)(SZ - 2));
        if (fast) {
            const int sx1 = ix1 - (x0 - HALO);
            const int sy1 = iy1 - (y0 - HALO);
            const int za  = sz0 * 4;
            const int zb  = (iz1 - (z0 - HALO)) * 4;

            const float* p00 = s + ((sx0 << 4) + sy0) * RS;
            const float* p01 = s + ((sx0 << 4) + sy1) * RS;
            const float* p10 = s + ((sx1 << 4) + sy0) * RS;
            const float* p11 = s + ((sx1 << 4) + sy1) * RS;

            // z = iz0 plane: bilinear in (x,y)
            const float4 A00 = *reinterpret_cast<const float4*>(p00 + za);
            const float4 A01 = *reinterpret_cast<const float4*>(p01 + za);
            const float4 A10 = *reinterpret_cast<const float4*>(p10 + za);
            const float4 A11 = *reinterpret_cast<const float4*>(p11 + za);
            const float s0x = (A00.x * wy0 + A01.x * wy) * wx0 +
                              (A10.x * wy0 + A11.x * wy) * wx;
            const float s0y = (A00.y * wy0 + A01.y * wy) * wx0 +
                              (A10.y * wy0 + A11.y * wy) * wx;
            const float s0z = (A00.z * wy0 + A01.z * wy) * wx0 +
                              (A10.z * wy0 + A11.z * wy) * wx;

            // z = iz1 plane
            const float4 B00 = *reinterpret_cast<const float4*>(p00 + zb);
            const float4 B01 = *reinterpret_cast<const float4*>(p01 + zb);
            const float4 B10 = *reinterpret_cast<const float4*>(p10 + zb);
            const float4 B11 = *reinterpret_cast<const float4*>(p11 + zb);
            const float s1x = (B00.x * wy0 + B01.x * wy) * wx0 +
                              (B10.x * wy0 + B11.x * wy) * wx;
            const float s1y = (B00.y * wy0 + B01.y * wy) * wx0 +
                              (B10.y * wy0 + B11.y * wy) * wx;
            const float s1z = (B00.z * wy0 + B01.z * wy) * wx0 +
                              (B10.z * wy0 + B11.z * wy) * wx;

            ox = s0x * wz0 + s1x * wz;
            oy = s0y * wz0 + s1y * wz;
            oz = s0z * wz0 + s1z * wz;
        } else {
            // Rare slow path (~0.04% of threads): direct global gather.
            float a0 = 0.f, a1 = 0.f, a2 = 0.f;
#pragma unroll
            for (int cx = 0; cx < 2; ++cx) {
                const int   ix  = cx ? ix1 : ix0;
                const float wxx = cx ? wx : wx0;
#pragma unroll
                for (int cy = 0; cy < 2; ++cy) {
                    const int   iy  = cy ? iy1 : iy0;
                    const float wxy = wxx * (cy ? wy : wy0);
#pragma unroll
                    for (int cz = 0; cz < 2; ++cz) {
                        const int   iz  = cz ? iz1 : iz0;
                        const float wgt = wxy * (cz ? wz : wz0);
                        const int off = ((ix * Hh + iy) * Ww + iz) * 3;
                        a0 = fmaf(__ldg(w1b + off + 0), wgt, a0);
                        a1 = fmaf(__ldg(w1b + off + 1), wgt, a1);
                        a2 = fmaf(__ldg(w1b + off + 2), wgt, a2);
                    }
                }
            }
            ox = a0; oy = a1; oz = a2;
        }

        out[f + 0] = u2x + ox;
        out[f + 1] = u2y + oy;
        out[f + 2] = u2z + oz;
    }
}

extern "C" void kernel_launch(void* const* d_in, const int* in_sizes, int n_in,
                              void* d_out, int out_size)
{
    const float* warp1 = (const float*)d_in[0];
    const float* warp2 = (const float*)d_in[1];
    float* out = (float*)d_out;

    static const size_t smem_bytes = BUF * sizeof(float);  // 110,592
    cudaFuncSetAttribute(compose_vec_kernel,
                         cudaFuncAttributeMaxDynamicSharedMemorySize,
                         (int)smem_bytes);

    // 16 x-tiles * 20 y-tiles = 320 xy tiles; 10 z chunks; 2 batches.
    dim3 grid(320, Ww / TZ, 2);
    compose_vec_kernel<<<grid, TPB, smem_bytes>>>(warp1, warp2, out);
}

// round 8
// speedup vs baseline: 1.3291x; 1.3291x over previous
#include <cuda_runtime.h>

// out = u2 + trilinear(u1, grid + u2), [B=2,160,160,160,3] fp32.
// One-shot smem tile per block, SoA layout: (x,y) as float2 plane, z as float
// plane -> 16 gather LDS per voxel (8x LDS.64 + 8x LDS.32), good banking.
// Tile sized so TWO blocks co-reside per SM.

#define Dd 160
#define Hh 160
#define Ww 160
#define HW  (Hh * Ww)
#define DHW (Dd * HW)

#define TX 10
#define TY 10
#define TZ 16
#define HALO 4
#define SX (TX + 2 * HALO)   // 18
#define SY (TY + 2 * HALO)   // 18
#define SZ (TZ + 2 * HALO)   // 24
#define NROW (SX * SY)       // 324
#define NVOXT (NROW * SZ)    // 7776 tile voxels
// smem: float2 xy plane (62,208 B) + float z plane (31,104 B) = 93,312 B
#define TPB 512
#define NWARP (TPB / 32)     // 16
#define NTASK (TX * (TY / 2))// 50 warp tasks: (x, y-pair)

extern __shared__ float smem[];

__global__ __launch_bounds__(TPB, 2)
void compose_soa_kernel(const float* __restrict__ w1,
                        const float* __restrict__ w2,
                        float* __restrict__ out)
{
    float2* __restrict__ s_xy = reinterpret_cast<float2*>(smem);
    float*  __restrict__ s_z  = smem + NVOXT * 2;

    // blockIdx.x = xy tile (x-major inner), .y = z chunk, .z = batch
    const int xt = blockIdx.x & 15;          // 0..15
    const int yt = blockIdx.x >> 4;          // 0..15
    const int x0 = xt * TX;
    const int y0 = yt * TY;
    const int z0 = blockIdx.y * TZ;
    const int b  = blockIdx.z;

    const int t    = threadIdx.x;
    const int lane = t & 31;
    const int wrp  = t >> 5;

    const float* __restrict__ w1b = w1 + (size_t)b * (size_t)DHW * 3;

    // ---- Tile fill: LDG.128 x3 -> SoA repack -> 4x STS.64 + 1x STS.128 ----
    // One group = 4 consecutive-z voxels of one (x,y) row.
    {
        const int zlo   = (z0 == 0) ? 0 : z0 - HALO;
        const int zhi   = (z0 + TZ + HALO > Ww) ? Ww : z0 + TZ + HALO;
        const int szb   = zlo - (z0 - HALO);       // 0 or 4
        const int ngrp  = (zhi - zlo) >> 2;        // 6 interior, 5 at z edges

#pragma unroll 1
        for (int idx = t; idx < NROW * 6; idx += TPB) {
            const int row = idx / 6;
            const int g   = idx - row * 6;
            if (g >= ngrp) continue;
            const int hx  = row / SY;
            const int hy  = row - hx * SY;
            const int cx  = x0 - HALO + hx;
            const int cy  = y0 - HALO + hy;
            if ((unsigned)cx < (unsigned)Dd && (unsigned)cy < (unsigned)Hh) {
                const float4* src = reinterpret_cast<const float4*>(
                    w1b + ((size_t)(cx * Hh + cy) * Ww + zlo + g * 4) * 3);
                const float4 a = src[0], c = src[1], d = src[2];
                // voxels v0..v3: xyz = (a.x a.y a.z)(a.w c.x c.y)(c.z c.w d.x)(d.y d.z d.w)
                const int vi = row * SZ + szb + g * 4;
                s_xy[vi + 0] = make_float2(a.x, a.y);
                s_xy[vi + 1] = make_float2(a.w, c.x);
                s_xy[vi + 2] = make_float2(c.z, c.w);
                s_xy[vi + 3] = make_float2(d.y, d.z);
                *reinterpret_cast<float4*>(s_z + vi) =
                    make_float4(a.z, c.y, d.x, d.w);
            }
        }
    }

    // ---- Compute mapping: lane = (ysub, z16); warp task = (x, y-pair) ----
    const int ysub = lane >> 4;          // 0..1
    const int hz   = lane & 15;          // 0..15
    const int z    = z0 + hz;

    // Prefetch first task's u2 (overlaps fill LDGs in flight).
    int task = wrp;
    int nf;
    float nux, nuy, nuz;
    {
        const int xi = task / 5, yp = task - xi * 5;
        nf  = (((b * Dd + x0 + xi) * Hh + y0 + yp * 2 + ysub) * Ww + z) * 3;
        nux = __ldg(w2 + nf + 0);
        nuy = __ldg(w2 + nf + 1);
        nuz = __ldg(w2 + nf + 2);
    }

    __syncthreads();

    for (; task < NTASK; task += NWARP) {
        const int xi = task / 5;
        const int x  = x0 + xi;
        const int y  = y0 + (task - xi * 5) * 2 + ysub;
        const int f  = nf;
        const float u2x = nux, u2y = nuy, u2z = nuz;

        if (task + NWARP < NTASK) {      // prefetch next task's u2
            const int xi2 = (task + NWARP) / 5;
            const int yp2 = (task + NWARP) - xi2 * 5;
            nf  = (((b * Dd + x0 + xi2) * Hh + y0 + yp2 * 2 + ysub) * Ww + z) * 3;
            nux = __ldg(w2 + nf + 0);
            nuy = __ldg(w2 + nf + 1);
            nuz = __ldg(w2 + nf + 2);
        }

        float lx = fminf(fmaxf((float)x + u2x, 0.0f), (float)(Dd - 1));
        float ly = fminf(fmaxf((float)y + u2y, 0.0f), (float)(Hh - 1));
        float lz = fminf(fmaxf((float)z + u2z, 0.0f), (float)(Ww - 1));

        const float fx = floorf(lx), fy = floorf(ly), fz = floorf(lz);
        const int ix0 = (int)fx, iy0 = (int)fy, iz0 = (int)fz;
        const float wx = lx - fx, wy = ly - fy, wz = lz - fz;
        const float wx0 = 1.0f - wx, wy0 = 1.0f - wy, wz0 = 1.0f - wz;

        const int ix1 = min(ix0 + 1, Dd - 1);
        const int iy1 = min(iy0 + 1, Hh - 1);
        const int iz1 = min(iz0 + 1, Ww - 1);

        const int sx0 = ix0 - (x0 - HALO);
        const int sy0 = iy0 - (y0 - HALO);
        const int sz0 = iz0 - (z0 - HALO);

        float ox, oy, oz;

        const bool fast = ((unsigned)sx0 <= (unsigned)(SX - 2)) &&
                          ((unsigned)sy0 <= (unsigned)(SY - 2)) &&
                          ((unsigned)sz0 <= (unsigned)(SZ - 2));
        if (fast) {
            const int sx1 = ix1 - (x0 - HALO);
            const int sy1 = iy1 - (y0 - HALO);
            const int sz1 = iz1 - (z0 - HALO);

            const int r00 = (sx0 * SY + sy0) * SZ;
            const int r01 = (sx0 * SY + sy1) * SZ;
            const int r10 = (sx1 * SY + sy0) * SZ;
            const int r11 = (sx1 * SY + sy1) * SZ;

            // z = iz0 plane
            const float2 A00 = s_xy[r00 + sz0];
            const float2 A01 = s_xy[r01 + sz0];
            const float2 A10 = s_xy[r10 + sz0];
            const float2 A11 = s_xy[r11 + sz0];
            const float  Z00 = s_z [r00 + sz0];
            const float  Z01 = s_z [r01 + sz0];
            const float  Z10 = s_z [r10 + sz0];
            const float  Z11 = s_z [r11 + sz0];
            // z = iz1 plane
            const float2 B00 = s_xy[r00 + sz1];
            const float2 B01 = s_xy[r01 + sz1];
            const float2 B10 = s_xy[r10 + sz1];
            const float2 B11 = s_xy[r11 + sz1];
            const float  W00 = s_z [r00 + sz1];
            const float  W01 = s_z [r01 + sz1];
            const float  W10 = s_z [r10 + sz1];
            const float  W11 = s_z [r11 + sz1];

            const float s0x = (A00.x * wy0 + A01.x * wy) * wx0 +
                              (A10.x * wy0 + A11.x * wy) * wx;
            const float s0y = (A00.y * wy0 + A01.y * wy) * wx0 +
                              (A10.y * wy0 + A11.y * wy) * wx;
            const float s0z = (Z00   * wy0 + Z01   * wy) * wx0 +
                              (Z10   * wy0 + Z11   * wy) * wx;
            const float s1x = (B00.x * wy0 + B01.x * wy) * wx0 +
                              (B10.x * wy0 + B11.x * wy) * wx;
            const float s1y = (B00.y * wy0 + B01.y * wy) * wx0 +
                              (B10.y * wy0 + B11.y * wy) * wx;
            const float s1z = (W00   * wy0 + W01   * wy) * wx0 +
                              (W10   * wy0 + W11   * wy) * wx;

            ox = s0x * wz0 + s1x * wz;
            oy = s0y * wz0 + s1y * wz;
            oz = s0z * wz0 + s1z * wz;
        } else {
            // Rare slow path (~0.02% of threads): direct global gather.
            float a0 = 0.f, a1 = 0.f, a2 = 0.f;
#pragma unroll
            for (int cx = 0; cx < 2; ++cx) {
                const int   ix  = cx ? ix1 : ix0;
                const float wxx = cx ? wx : wx0;
#pragma unroll
                for (int cy = 0; cy < 2; ++cy) {
                    const int   iy  = cy ? iy1 : iy0;
                    const float wxy = wxx * (cy ? wy : wy0);
#pragma unroll
                    for (int cz = 0; cz < 2; ++cz) {
                        const int   iz  = cz ? iz1 : iz0;
                        const float wgt = wxy * (cz ? wz : wz0);
                        const int off = ((ix * Hh + iy) * Ww + iz) * 3;
                        a0 = fmaf(__ldg(w1b + off + 0), wgt, a0);
                        a1 = fmaf(__ldg(w1b + off + 1), wgt, a1);
                        a2 = fmaf(__ldg(w1b + off + 2), wgt, a2);
                    }
                }
            }
            ox = a0; oy = a1; oz = a2;
        }

        out[f + 0] = u2x + ox;
        out[f + 1] = u2y + oy;
        out[f + 2] = u2z + oz;
    }
}

extern "C" void kernel_launch(void* const* d_in, const int* in_sizes, int n_in,
                              void* d_out, int out_size)
{
    const float* warp1 = (const float*)d_in[0];
    const float* warp2 = (const float*)d_in[1];
    float* out = (float*)d_out;

    static const size_t smem_bytes = NVOXT * 3 * sizeof(float);  // 93,312
    cudaFuncSetAttribute(compose_soa_kernel,
                         cudaFuncAttributeMaxDynamicSharedMemorySize,
                         (int)smem_bytes);

    // 256 xy tiles (x-major), 10 z chunks, 2 batches = 5120 blocks.
    dim3 grid(256, Ww / TZ, 2);
    compose_soa_kernel<<<grid, TPB, smem_bytes>>>(warp1, warp2, out);
}

// round 9
// speedup vs baseline: 1.5584x; 1.1726x over previous
#include <cuda_runtime.h>

// out = u2 + trilinear(u1, grid + u2), [B=2,160,160,160,3] fp32.
// R6 tile layout (scalar stride-3 smem, best gather banking) + u2/out staged
// through smem so ALL global traffic is float4-coalesced.
// Two blocks co-reside per SM.

#define Dd 160
#define Hh 160
#define Ww 160
#define HW  (Hh * Ww)
#define DHW (Dd * HW)

#define TX 10
#define TY 10
#define TZ 16
#define HALO 4
#define SX (TX + 2 * HALO)   // 18
#define SY (TY + 2 * HALO)   // 18
#define SZ (TZ + 2 * HALO)   // 24
#define RS (SZ * 3)          // 72 floats per (x,y) tile row
#define NROW (SX * SY)       // 324
#define BUF (NROW * RS)      // 23328 floats = 93,312 B
#define UROW (TZ * 3)        // 48 floats per u2 row
#define NU2  (TX * TY * UROW)// 4800 floats = 19,200 B
#define TPB 512
#define NWARP (TPB / 32)     // 16
#define NTASK (TX * (TY / 2))// 50 warp tasks: (x, y-pair)

extern __shared__ float smem[];   // [BUF w1-tile][NU2 u2/out staging]

__device__ __forceinline__ void cp16(float* smem_dst, const float* gsrc)
{
    unsigned saddr = (unsigned)__cvta_generic_to_shared(smem_dst);
    asm volatile("cp.async.cg.shared.global [%0], [%1], 16;\n"
                 :: "r"(saddr), "l"(gsrc));
}

__global__ __launch_bounds__(TPB, 2)
void compose_stage_kernel(const float* __restrict__ w1,
                          const float* __restrict__ w2,
                          float* __restrict__ out)
{
    float* __restrict__ s   = smem;        // w1 tile
    float* __restrict__ su  = smem + BUF;  // u2 in / result out staging

    // blockIdx.x = xy tile (x-major inner), .y = z chunk, .z = batch
    const int xt = blockIdx.x & 15;          // 0..15
    const int yt = blockIdx.x >> 4;          // 0..15
    const int x0 = xt * TX;
    const int y0 = yt * TY;
    const int z0 = blockIdx.y * TZ;
    const int b  = blockIdx.z;

    const int t    = threadIdx.x;
    const int lane = t & 31;
    const int wrp  = t >> 5;

    const float* __restrict__ w1b = w1 + (size_t)b * (size_t)DHW * 3;

    // ---- w1 tile fill via cp.async (flat row,vec indexing) ----
    if (z0 >= HALO && z0 + TZ + HALO <= Ww) {
        const size_t zoff = (size_t)(z0 - HALO) * 3;
        for (int idx = t; idx < NROW * 18; idx += TPB) {
            const int row = idx / 18;
            const int v   = idx - row * 18;
            const int hx  = row / SY;
            const int hy  = row - hx * SY;
            const int cx  = x0 - HALO + hx;
            const int cy  = y0 - HALO + hy;
            if ((unsigned)cx < (unsigned)Dd && (unsigned)cy < (unsigned)Hh)
                cp16(s + row * RS + v * 4,
                     w1b + (size_t)(cx * Hh + cy) * (Ww * 3) + zoff + v * 4);
        }
    } else {
        const int zlo  = (z0 == 0) ? 0 : z0 - HALO;
        const int dsto = (z0 == 0) ? 12 : 0;
        const size_t zoff = (size_t)zlo * 3;
        for (int idx = t; idx < NROW * 15; idx += TPB) {
            const int row = idx / 15;
            const int v   = idx - row * 15;
            const int hx  = row / SY;
            const int hy  = row - hx * SY;
            const int cx  = x0 - HALO + hx;
            const int cy  = y0 - HALO + hy;
            if ((unsigned)cx < (unsigned)Dd && (unsigned)cy < (unsigned)Hh)
                cp16(s + row * RS + dsto + v * 4,
                     w1b + (size_t)(cx * Hh + cy) * (Ww * 3) + zoff + v * 4);
        }
    }

    // ---- u2 subtile fill via cp.async (fully coalesced 16B) ----
    {
        const float* __restrict__ w2b = w2 + (size_t)b * (size_t)DHW * 3;
        for (int idx = t; idx < (NU2 / 4); idx += TPB) {   // 1200 vecs
            const int row = idx / 12;                      // 0..99 = xi*10+yi
            const int v   = idx - row * 12;
            const int xi  = row / TY;
            const int yi  = row - xi * TY;
            cp16(su + row * UROW + v * 4,
                 w2b + ((size_t)((x0 + xi) * Hh + y0 + yi) * Ww + z0) * 3 + v * 4);
        }
    }
    asm volatile("cp.async.commit_group;\n" ::: "memory");

    // ---- Compute mapping: lane = (ysub, z16); warp task = (x, y-pair) ----
    const int ysub = lane >> 4;          // 0..1
    const int hz   = lane & 15;          // 0..15
    const int z    = z0 + hz;

    asm volatile("cp.async.wait_group 0;\n" ::: "memory");
    __syncthreads();

    for (int task = wrp; task < NTASK; task += NWARP) {
        const int xi = task / 5;
        const int yp = task - xi * 5;
        const int x  = x0 + xi;
        const int y  = y0 + yp * 2 + ysub;

        float* __restrict__ uslot =
            su + (xi * TY + yp * 2 + ysub) * UROW + hz * 3;
        const float u2x = uslot[0];
        const float u2y = uslot[1];
        const float u2z = uslot[2];

        float lx = fminf(fmaxf((float)x + u2x, 0.0f), (float)(Dd - 1));
        float ly = fminf(fmaxf((float)y + u2y, 0.0f), (float)(Hh - 1));
        float lz = fminf(fmaxf((float)z + u2z, 0.0f), (float)(Ww - 1));

        const float fx = floorf(lx), fy = floorf(ly), fz = floorf(lz);
        const int ix0 = (int)fx, iy0 = (int)fy, iz0 = (int)fz;
        const float wx = lx - fx, wy = ly - fy, wz = lz - fz;
        const float wx0 = 1.0f - wx, wy0 = 1.0f - wy, wz0 = 1.0f - wz;

        const int ix1 = min(ix0 + 1, Dd - 1);
        const int iy1 = min(iy0 + 1, Hh - 1);
        const int iz1 = min(iz0 + 1, Ww - 1);

        const int sx0 = ix0 - (x0 - HALO);
        const int sy0 = iy0 - (y0 - HALO);
        const int sz0 = iz0 - (z0 - HALO);

        float ox, oy, oz;

        const bool fast = ((unsigned)sx0 <= (unsigned)(SX - 2)) &&
                          ((unsigned)sy0 <= (unsigned)(SY - 2)) &&
                          ((unsigned)sz0 <= (unsigned)(SZ - 2));
        if (fast) {
            const int sx1 = ix1 - (x0 - HALO);
            const int sy1 = iy1 - (y0 - HALO);
            const int za  = sz0 * 3;
            const int zb  = (iz1 - (z0 - HALO)) * 3;

            const float* p00 = s + (sx0 * SY + sy0) * RS;
            const float* p01 = s + (sx0 * SY + sy1) * RS;
            const float* p10 = s + (sx1 * SY + sy0) * RS;
            const float* p11 = s + (sx1 * SY + sy1) * RS;

            float acc[3];
#pragma unroll
            for (int c = 0; c < 3; ++c) {
                const float v00 = p00[za + c] * wz0 + p00[zb + c] * wz;
                const float v01 = p01[za + c] * wz0 + p01[zb + c] * wz;
                const float v10 = p10[za + c] * wz0 + p10[zb + c] * wz;
                const float v11 = p11[za + c] * wz0 + p11[zb + c] * wz;
                acc[c] = (v00 * wy0 + v01 * wy) * wx0 +
                         (v10 * wy0 + v11 * wy) * wx;
            }
            ox = acc[0]; oy = acc[1]; oz = acc[2];
        } else {
            // Rare slow path (~0.02% of threads): direct global gather.
            float a0 = 0.f, a1 = 0.f, a2 = 0.f;
#pragma unroll
            for (int cx = 0; cx < 2; ++cx) {
                const int   ix  = cx ? ix1 : ix0;
                const float wxx = cx ? wx : wx0;
#pragma unroll
                for (int cy = 0; cy < 2; ++cy) {
                    const int   iy  = cy ? iy1 : iy0;
                    const float wxy = wxx * (cy ? wy : wy0);
#pragma unroll
                    for (int cz = 0; cz < 2; ++cz) {
                        const int   iz  = cz ? iz1 : iz0;
                        const float wgt = wxy * (cz ? wz : wz0);
                        const int off = ((ix * Hh + iy) * Ww + iz) * 3;
                        a0 = fmaf(__ldg(w1b + off + 0), wgt, a0);
                        a1 = fmaf(__ldg(w1b + off + 1), wgt, a1);
                        a2 = fmaf(__ldg(w1b + off + 2), wgt, a2);
                    }
                }
            }
            ox = a0; oy = a1; oz = a2;
        }

        // In-place: this thread exclusively owns these 3 staging slots.
        uslot[0] = u2x + ox;
        uslot[1] = u2y + oy;
        uslot[2] = u2z + oz;
    }

    __syncthreads();

    // ---- Bulk coalesced store: staging -> out as float4 ----
    {
        float* __restrict__ outb = out + (size_t)b * (size_t)DHW * 3;
        for (int idx = t; idx < (NU2 / 4); idx += TPB) {   // 1200 vecs
            const int row = idx / 12;
            const int v   = idx - row * 12;
            const int xi  = row / TY;
            const int yi  = row - xi * TY;
            float4* dst = reinterpret_cast<float4*>(
                outb + ((size_t)((x0 + xi) * Hh + y0 + yi) * Ww + z0) * 3) + v;
            *dst = *(reinterpret_cast<const float4*>(su + row * UROW) + v);
        }
    }
}

extern "C" void kernel_launch(void* const* d_in, const int* in_sizes, int n_in,
                              void* d_out, int out_size)
{
    const float* warp1 = (const float*)d_in[0];
    const float* warp2 = (const float*)d_in[1];
    float* out = (float*)d_out;

    static const size_t smem_bytes = (BUF + NU2) * sizeof(float);  // 112,512
    cudaFuncSetAttribute(compose_stage_kernel,
                         cudaFuncAttributeMaxDynamicSharedMemorySize,
                         (int)smem_bytes);

    // 256 xy tiles (x-major), 10 z chunks, 2 batches = 5120 blocks.
    dim3 grid(256, Ww / TZ, 2);
    compose_stage_kernel<<<grid, TPB, smem_bytes>>>(warp1, warp2, out);
}

// round 10
// speedup vs baseline: 1.7124x; 1.0988x over previous
#include <cuda_runtime.h>

// out = u2 + trilinear(u1, grid + u2), [B=2,160,160,160,3] fp32.
// R6 structure, but warps pair two X rows instead of two Y rows:
// bank math (SY*RS=16 mod 32) makes the 24 gather LDS near conflict-free.
// Two blocks co-reside per SM.

#define Dd 160
#define Hh 160
#define Ww 160
#define HW  (Hh * Ww)
#define DHW (Dd * HW)

#define TX 10
#define TY 10
#define TZ 16
#define HALO 4
#define SX (TX + 2 * HALO)   // 18
#define SY (TY + 2 * HALO)   // 18
#define SZ (TZ + 2 * HALO)   // 24
#define RS (SZ * 3)          // 72 floats per (x,y) row  (== 8 mod 32)
#define NROW (SX * SY)       // 324
#define BUF (NROW * RS)      // 23328 floats = 93,312 B
#define TPB 512
#define NWARP (TPB / 32)     // 16
#define NTASK ((TX / 2) * TY)// 50 warp tasks: (x-pair, y)

extern __shared__ float s[];

__device__ __forceinline__ void cp16(float* smem_dst, const float* gsrc)
{
    unsigned saddr = (unsigned)__cvta_generic_to_shared(smem_dst);
    asm volatile("cp.async.cg.shared.global [%0], [%1], 16;\n"
                 :: "r"(saddr), "l"(gsrc));
}

__global__ __launch_bounds__(TPB, 2)
void compose_xpair_kernel(const float* __restrict__ w1,
                          const float* __restrict__ w2,
                          float* __restrict__ out)
{
    // blockIdx.x = xy tile (x-major inner), .y = z chunk, .z = batch
    const int xt = blockIdx.x & 15;          // 0..15
    const int yt = blockIdx.x >> 4;          // 0..15
    const int x0 = xt * TX;
    const int y0 = yt * TY;
    const int z0 = blockIdx.y * TZ;
    const int b  = blockIdx.z;

    const int t    = threadIdx.x;
    const int lane = t & 31;
    const int wrp  = t >> 5;

    const float* __restrict__ w1b = w1 + (size_t)b * (size_t)DHW * 3;

    // ---- One-shot tile fill via cp.async, flat (row, vec) indexing ----
    if (z0 >= HALO && z0 + TZ + HALO <= Ww) {
        const size_t zoff = (size_t)(z0 - HALO) * 3;
        for (int idx = t; idx < NROW * 18; idx += TPB) {
            const int row = idx / 18;
            const int v   = idx - row * 18;
            const int hx  = row / SY;
            const int hy  = row - hx * SY;
            const int cx  = x0 - HALO + hx;
            const int cy  = y0 - HALO + hy;
            if ((unsigned)cx < (unsigned)Dd && (unsigned)cy < (unsigned)Hh)
                cp16(s + row * RS + v * 4,
                     w1b + (size_t)(cx * Hh + cy) * (Ww * 3) + zoff + v * 4);
        }
    } else {
        const int zlo  = (z0 == 0) ? 0 : z0 - HALO;
        const int dsto = (z0 == 0) ? 12 : 0;
        const size_t zoff = (size_t)zlo * 3;
        for (int idx = t; idx < NROW * 15; idx += TPB) {
            const int row = idx / 15;
            const int v   = idx - row * 15;
            const int hx  = row / SY;
            const int hy  = row - hx * SY;
            const int cx  = x0 - HALO + hx;
            const int cy  = y0 - HALO + hy;
            if ((unsigned)cx < (unsigned)Dd && (unsigned)cy < (unsigned)Hh)
                cp16(s + row * RS + dsto + v * 4,
                     w1b + (size_t)(cx * Hh + cy) * (Ww * 3) + zoff + v * 4);
        }
    }
    asm volatile("cp.async.commit_group;\n" ::: "memory");

    // ---- Compute mapping: lane = (xsub, z16); warp task = (x-pair, y) ----
    const int xsub = lane >> 4;          // 0..1
    const int hz   = lane & 15;          // 0..15
    const int z    = z0 + hz;

    // Prefetch first task's u2 while the tile streams in.
    int task = wrp;
    int nf;
    float nux, nuy, nuz;
    {
        const int xp = task / 10, yi = task - xp * 10;
        nf  = (((b * Dd + x0 + xp * 2 + xsub) * Hh + y0 + yi) * Ww + z) * 3;
        nux = __ldg(w2 + nf + 0);
        nuy = __ldg(w2 + nf + 1);
        nuz = __ldg(w2 + nf + 2);
    }

    asm volatile("cp.async.wait_group 0;\n" ::: "memory");
    __syncthreads();

    for (; task < NTASK; task += NWARP) {
        const int xp = task / 10;
        const int x  = x0 + xp * 2 + xsub;
        const int y  = y0 + (task - xp * 10);
        const int f  = nf;
        const float u2x = nux, u2y = nuy, u2z = nuz;

        if (task + NWARP < NTASK) {      // prefetch next task's u2
            const int nt  = task + NWARP;
            const int xp2 = nt / 10;
            nf  = (((b * Dd + x0 + xp2 * 2 + xsub) * Hh +
                    y0 + (nt - xp2 * 10)) * Ww + z) * 3;
            nux = __ldg(w2 + nf + 0);
            nuy = __ldg(w2 + nf + 1);
            nuz = __ldg(w2 + nf + 2);
        }

        float lx = fminf(fmaxf((float)x + u2x, 0.0f), (float)(Dd - 1));
        float ly = fminf(fmaxf((float)y + u2y, 0.0f), (float)(Hh - 1));
        float lz = fminf(fmaxf((float)z + u2z, 0.0f), (float)(Ww - 1));

        const float fx = floorf(lx), fy = floorf(ly), fz = floorf(lz);
        const int ix0 = (int)fx, iy0 = (int)fy, iz0 = (int)fz;
        const float wx = lx - fx, wy = ly - fy, wz = lz - fz;
        const float wx0 = 1.0f - wx, wy0 = 1.0f - wy, wz0 = 1.0f - wz;

        const int ix1 = min(ix0 + 1, Dd - 1);
        const int iy1 = min(iy0 + 1, Hh - 1);
        const int iz1 = min(iz0 + 1, Ww - 1);

        const int sx0 = ix0 - (x0 - HALO);
        const int sy0 = iy0 - (y0 - HALO);
        const int sz0 = iz0 - (z0 - HALO);

        float ox, oy, oz;

        const bool fast = ((unsigned)sx0 <= (unsigned)(SX - 2)) &&
                          ((unsigned)sy0 <= (unsigned)(SY - 2)) &&
                          ((unsigned)sz0 <= (unsigned)(SZ - 2));
        if (fast) {
            const int sx1 = ix1 - (x0 - HALO);
            const int sy1 = iy1 - (y0 - HALO);
            const int za  = sz0 * 3;
            const int zb  = (iz1 - (z0 - HALO)) * 3;

            const float* p00 = s + (sx0 * SY + sy0) * RS;
            const float* p01 = s + (sx0 * SY + sy1) * RS;
            const float* p10 = s + (sx1 * SY + sy0) * RS;
            const float* p11 = s + (sx1 * SY + sy1) * RS;

            float acc[3];
#pragma unroll
            for (int c = 0; c < 3; ++c) {
                const float v00 = p00[za + c] * wz0 + p00[zb + c] * wz;
                const float v01 = p01[za + c] * wz0 + p01[zb + c] * wz;
                const float v10 = p10[za + c] * wz0 + p10[zb + c] * wz;
                const float v11 = p11[za + c] * wz0 + p11[zb + c] * wz;
                acc[c] = (v00 * wy0 + v01 * wy) * wx0 +
                         (v10 * wy0 + v11 * wy) * wx;
            }
            ox = acc[0]; oy = acc[1]; oz = acc[2];
        } else {
            // Rare slow path (~0.02% of threads): direct global gather.
            float a0 = 0.f, a1 = 0.f, a2 = 0.f;
#pragma unroll
            for (int cx = 0; cx < 2; ++cx) {
                const int   ix  = cx ? ix1 : ix0;
                const float wxx = cx ? wx : wx0;
#pragma unroll
                for (int cy = 0; cy < 2; ++cy) {
                    const int   iy  = cy ? iy1 : iy0;
                    const float wxy = wxx * (cy ? wy : wy0);
#pragma unroll
                    for (int cz = 0; cz < 2; ++cz) {
                        const int   iz  = cz ? iz1 : iz0;
                        const float wgt = wxy * (cz ? wz : wz0);
                        const int off = ((ix * Hh + iy) * Ww + iz) * 3;
                        a0 = fmaf(__ldg(w1b + off + 0), wgt, a0);
                        a1 = fmaf(__ldg(w1b + off + 1), wgt, a1);
                        a2 = fmaf(__ldg(w1b + off + 2), wgt, a2);
                    }
                }
            }
            ox = a0; oy = a1; oz = a2;
        }

        out[f + 0] = u2x + ox;
        out[f + 1] = u2y + oy;
        out[f + 2] = u2z + oz;
    }
}

extern "C" void kernel_launch(void* const* d_in, const int* in_sizes, int n_in,
                              void* d_out, int out_size)
{
    const float* warp1 = (const float*)d_in[0];
    const float* warp2 = (const float*)d_in[1];
    float* out = (float*)d_out;

    static const size_t smem_bytes = BUF * sizeof(float);  // 93,312
    cudaFuncSetAttribute(compose_xpair_kernel,
                         cudaFuncAttributeMaxDynamicSharedMemorySize,
                         (int)smem_bytes);

    // 256 xy tiles (x-major), 10 z chunks, 2 batches = 5120 blocks.
    dim3 grid(256, Ww / TZ, 2);
    compose_xpair_kernel<<<grid, TPB, smem_bytes>>>(warp1, warp2, out);
}

// round 11
// speedup vs baseline: 1.7141x; 1.0010x over previous
#include <cuda_runtime.h>

// out = u2 + trilinear(u1, grid + u2), [B=2,160,160,160,3] fp32.
// R10 structure (x-paired warps, best gather banking) + magic-number floor
// (no F2I/I2F latency chain) + dropped index clamps + streaming out stores.
// Two blocks co-reside per SM.

#define Dd 160
#define Hh 160
#define Ww 160
#define HW  (Hh * Ww)
#define DHW (Dd * HW)

#define TX 10
#define TY 10
#define TZ 16
#define HALO 4
#define SX (TX + 2 * HALO)   // 18
#define SY (TY + 2 * HALO)   // 18
#define SZ (TZ + 2 * HALO)   // 24
#define RS (SZ * 3)          // 72 floats per (x,y) row (== 8 mod 32)
#define NROW (SX * SY)       // 324
#define BUF (NROW * RS)      // 23328 floats = 93,312 B
#define TPB 512
#define NWARP (TPB / 32)     // 16
#define NTASK ((TX / 2) * TY)// 50 warp tasks: (x-pair, y)

#define MAGIC 12582912.0f    // 1.5 * 2^23
#define MAGIC_I 0x4B400000

extern __shared__ float s[];

__device__ __forceinline__ void cp16(float* smem_dst, const float* gsrc)
{
    unsigned saddr = (unsigned)__cvta_generic_to_shared(smem_dst);
    asm volatile("cp.async.cg.shared.global [%0], [%1], 16;\n"
                 :: "r"(saddr), "l"(gsrc));
}

// floor for v in [0, 160): returns i = floor-ish(v) (continuity-safe) and
// f = (float)i, using only FADD/IADD latency (no F2I/I2F).
__device__ __forceinline__ void fast_floor(float v, int& i, float& f)
{
    const float fm = (v - 0.5f) + MAGIC;    // round-to-even(v-0.5) + MAGIC
    i = __float_as_int(fm) - MAGIC_I;
    f = fm - MAGIC;
}

__global__ __launch_bounds__(TPB, 2)
void compose_magic_kernel(const float* __restrict__ w1,
                          const float* __restrict__ w2,
                          float* __restrict__ out)
{
    // blockIdx.x = xy tile (x-major inner), .y = z chunk, .z = batch
    const int xt = blockIdx.x & 15;          // 0..15
    const int yt = blockIdx.x >> 4;          // 0..15
    const int x0 = xt * TX;
    const int y0 = yt * TY;
    const int z0 = blockIdx.y * TZ;
    const int b  = blockIdx.z;

    const int t    = threadIdx.x;
    const int lane = t & 31;
    const int wrp  = t >> 5;

    const float* __restrict__ w1b = w1 + (size_t)b * (size_t)DHW * 3;

    // ---- One-shot tile fill via cp.async, flat (row, vec) indexing ----
    if (z0 >= HALO && z0 + TZ + HALO <= Ww) {
        const size_t zoff = (size_t)(z0 - HALO) * 3;
        for (int idx = t; idx < NROW * 18; idx += TPB) {
            const int row = idx / 18;
            const int v   = idx - row * 18;
            const int hx  = row / SY;
            const int hy  = row - hx * SY;
            const int cx  = x0 - HALO + hx;
            const int cy  = y0 - HALO + hy;
            if ((unsigned)cx < (unsigned)Dd && (unsigned)cy < (unsigned)Hh)
                cp16(s + row * RS + v * 4,
                     w1b + (size_t)(cx * Hh + cy) * (Ww * 3) + zoff + v * 4);
        }
    } else {
        const int zlo  = (z0 == 0) ? 0 : z0 - HALO;
        const int dsto = (z0 == 0) ? 12 : 0;
        const size_t zoff = (size_t)zlo * 3;
        for (int idx = t; idx < NROW * 15; idx += TPB) {
            const int row = idx / 15;
            const int v   = idx - row * 15;
            const int hx  = row / SY;
            const int hy  = row - hx * SY;
            const int cx  = x0 - HALO + hx;
            const int cy  = y0 - HALO + hy;
            if ((unsigned)cx < (unsigned)Dd && (unsigned)cy < (unsigned)Hh)
                cp16(s + row * RS + dsto + v * 4,
                     w1b + (size_t)(cx * Hh + cy) * (Ww * 3) + zoff + v * 4);
        }
    }
    asm volatile("cp.async.commit_group;\n" ::: "memory");

    // ---- Compute mapping: lane = (xsub, z16); warp task = (x-pair, y) ----
    const int xsub = lane >> 4;          // 0..1
    const int hz   = lane & 15;          // 0..15
    const int z    = z0 + hz;

    // Prefetch first task's u2 while the tile streams in.
    int task = wrp;
    int nf;
    float nux, nuy, nuz;
    {
        const int xp = task / 10, yi = task - xp * 10;
        nf  = (((b * Dd + x0 + xp * 2 + xsub) * Hh + y0 + yi) * Ww + z) * 3;
        nux = __ldg(w2 + nf + 0);
        nuy = __ldg(w2 + nf + 1);
        nuz = __ldg(w2 + nf + 2);
    }

    asm volatile("cp.async.wait_group 0;\n" ::: "memory");
    __syncthreads();

    for (; task < NTASK; task += NWARP) {
        const int xp = task / 10;
        const int x  = x0 + xp * 2 + xsub;
        const int y  = y0 + (task - xp * 10);
        const int f  = nf;
        const float u2x = nux, u2y = nuy, u2z = nuz;

        if (task + NWARP < NTASK) {      // prefetch next task's u2
            const int nt  = task + NWARP;
            const int xp2 = nt / 10;
            nf  = (((b * Dd + x0 + xp2 * 2 + xsub) * Hh +
                    y0 + (nt - xp2 * 10)) * Ww + z) * 3;
            nux = __ldg(w2 + nf + 0);
            nuy = __ldg(w2 + nf + 1);
            nuz = __ldg(w2 + nf + 2);
        }

        const float lx = fminf(fmaxf((float)x + u2x, 0.0f), (float)(Dd - 1));
        const float ly = fminf(fmaxf((float)y + u2y, 0.0f), (float)(Hh - 1));
        const float lz = fminf(fmaxf((float)z + u2z, 0.0f), (float)(Ww - 1));

        int ix0, iy0, iz0;
        float fx, fy, fz;
        fast_floor(lx, ix0, fx);
        fast_floor(ly, iy0, fy);
        fast_floor(lz, iz0, fz);
        const float wx = lx - fx, wy = ly - fy, wz = lz - fz;
        const float wx0 = 1.0f - wx, wy0 = 1.0f - wy, wz0 = 1.0f - wz;
        // l <= 159 => i0 <= 158 => i1 = i0+1 <= 159: no clamp needed.

        const int sx0 = ix0 - (x0 - HALO);
        const int sy0 = iy0 - (y0 - HALO);
        const int sz0 = iz0 - (z0 - HALO);

        float ox, oy, oz;

        const bool fast = ((unsigned)sx0 <= (unsigned)(SX - 2)) &&
                          ((unsigned)sy0 <= (unsigned)(SY - 2)) &&
                          ((unsigned)sz0 <= (unsigned)(SZ - 2));
        if (fast) {
            const int za = sz0 * 3;
            const int zb = za + 3;

            const float* p00 = s + (sx0 * SY + sy0) * RS;
            const float* p01 = p00 + RS;                    // sy0+1
            const float* p10 = p00 + SY * RS;               // sx0+1
            const float* p11 = p10 + RS;

            float acc[3];
#pragma unroll
            for (int c = 0; c < 3; ++c) {
                const float v00 = p00[za + c] * wz0 + p00[zb + c] * wz;
                const float v01 = p01[za + c] * wz0 + p01[zb + c] * wz;
                const float v10 = p10[za + c] * wz0 + p10[zb + c] * wz;
                const float v11 = p11[za + c] * wz0 + p11[zb + c] * wz;
                acc[c] = (v00 * wy0 + v01 * wy) * wx0 +
                         (v10 * wy0 + v11 * wy) * wx;
            }
            ox = acc[0]; oy = acc[1]; oz = acc[2];
        } else {
            // Rare slow path (~0.02% of threads): direct global gather.
            const int ix1 = min(ix0 + 1, Dd - 1);
            const int iy1 = min(iy0 + 1, Hh - 1);
            const int iz1 = min(iz0 + 1, Ww - 1);
            float a0 = 0.f, a1 = 0.f, a2 = 0.f;
#pragma unroll
            for (int cx = 0; cx < 2; ++cx) {
                const int   ix  = cx ? ix1 : ix0;
                const float wxx = cx ? wx : wx0;
#pragma unroll
                for (int cy = 0; cy < 2; ++cy) {
                    const int   iy  = cy ? iy1 : iy0;
                    const float wxy = wxx * (cy ? wy : wy0);
#pragma unroll
                    for (int cz = 0; cz < 2; ++cz) {
                        const int   iz  = cz ? iz1 : iz0;
                        const float wgt = wxy * (cz ? wz : wz0);
                        const int off = ((ix * Hh + iy) * Ww + iz) * 3;
                        a0 = fmaf(__ldg(w1b + off + 0), wgt, a0);
                        a1 = fmaf(__ldg(w1b + off + 1), wgt, a1);
                        a2 = fmaf(__ldg(w1b + off + 2), wgt, a2);
                    }
                }
            }
            ox = a0; oy = a1; oz = a2;
        }

        __stcs(out + f + 0, u2x + ox);
        __stcs(out + f + 1, u2y + oy);
        __stcs(out + f + 2, u2z + oz);
    }
}

extern "C" void kernel_launch(void* const* d_in, const int* in_sizes, int n_in,
                              void* d_out, int out_size)
{
    const float* warp1 = (const float*)d_in[0];
    const float* warp2 = (const float*)d_in[1];
    float* out = (float*)d_out;

    static const size_t smem_bytes = BUF * sizeof(float);  // 93,312
    cudaFuncSetAttribute(compose_magic_kernel,
                         cudaFuncAttributeMaxDynamicSharedMemorySize,
                         (int)smem_bytes);

    // 256 xy tiles (x-major), 10 z chunks, 2 batches = 5120 blocks.
    dim3 grid(256, Ww / TZ, 2);
    compose_magic_kernel<<<grid, TPB, smem_bytes>>>(warp1, warp2, out);
}

// round 12
// speedup vs baseline: 2.0305x; 1.1846x over previous
#include <cuda_runtime.h>
#include <cstdint>

// out = u2 + trilinear(u1, grid + u2), [B=2,160,160,160,3] fp32.
// R11 structure, but the smem tile is filled with per-row cp.async.bulk
// (288B/240B contiguous, 16B-aligned both sides) + one mbarrier, removing
// ~2600 per-16B cp.async L1 wavefronts and their index ALU per block.
// Two blocks co-reside per SM.

#define Dd 160
#define Hh 160
#define Ww 160
#define HW  (Hh * Ww)
#define DHW (Dd * HW)

#define TX 10
#define TY 10
#define TZ 16
#define HALO 4
#define SX (TX + 2 * HALO)   // 18
#define SY (TY + 2 * HALO)   // 18
#define SZ (TZ + 2 * HALO)   // 24
#define RS (SZ * 3)          // 72 floats per (x,y) row (== 8 mod 32)
#define NROW (SX * SY)       // 324
#define BUF (NROW * RS)      // 23328 floats = 93,312 B
#define TPB 512
#define NWARP (TPB / 32)     // 16
#define NTASK ((TX / 2) * TY)// 50 warp tasks: (x-pair, y)

#define MAGIC 12582912.0f    // 1.5 * 2^23
#define MAGIC_I 0x4B400000

extern __shared__ float s[];   // [BUF floats][8B mbarrier]

__device__ __forceinline__ void fast_floor(float v, int& i, float& f)
{
    const float fm = (v - 0.5f) + MAGIC;    // round-to-even(v-0.5) + MAGIC
    i = __float_as_int(fm) - MAGIC_I;
    f = fm - MAGIC;
}

__global__ __launch_bounds__(TPB, 2)
void compose_bulk_kernel(const float* __restrict__ w1,
                         const float* __restrict__ w2,
                         float* __restrict__ out)
{
    // blockIdx.x = xy tile (x-major inner), .y = z chunk, .z = batch
    const int xt = blockIdx.x & 15;          // 0..15
    const int yt = blockIdx.x >> 4;          // 0..15
    const int x0 = xt * TX;
    const int y0 = yt * TY;
    const int z0 = blockIdx.y * TZ;
    const int b  = blockIdx.z;

    const int t    = threadIdx.x;
    const int lane = t & 31;
    const int wrp  = t >> 5;

    const float* __restrict__ w1b = w1 + (size_t)b * (size_t)DHW * 3;

    const uint32_t mbar = (uint32_t)__cvta_generic_to_shared(s + BUF);
    const uint32_t sbase = (uint32_t)__cvta_generic_to_shared(s);

    // z-range of the tile fill (contiguous per row, 16B aligned both sides)
    const int zlo    = (z0 == 0) ? 0 : z0 - HALO;
    const int zhi    = (z0 + TZ + HALO > Ww) ? Ww : z0 + TZ + HALO;
    const int nbytes = (zhi - zlo) * 12;            // 288 or 240
    const int dstob  = (zlo - (z0 - HALO)) * 12;    // 0 or 48 bytes

    // valid (x,y) row counts for expect_tx
    const int xlo = (x0 - HALO < 0) ? 0 : x0 - HALO;
    const int xhi = (x0 + TX + HALO > Dd) ? Dd : x0 + TX + HALO;
    const int ylo = (y0 - HALO < 0) ? 0 : y0 - HALO;
    const int yhi = (y0 + TY + HALO > Hh) ? Hh : y0 + TY + HALO;
    const unsigned total_tx = (unsigned)((xhi - xlo) * (yhi - ylo) * nbytes);

    if (t == 0) {
        asm volatile("mbarrier.init.shared.b64 [%0], 1;"
                     :: "r"(mbar) : "memory");
    }
    __syncthreads();
    if (t == 0) {
        asm volatile("mbarrier.arrive.expect_tx.shared.b64 _, [%0], %1;"
                     :: "r"(mbar), "r"(total_tx) : "memory");
    }

    // ---- Tile fill: one 288B/240B bulk copy per (x,y) row ----
    if (t < NROW) {
        const int hx = t / SY;
        const int hy = t - hx * SY;
        const int cx = x0 - HALO + hx;
        const int cy = y0 - HALO + hy;
        if ((unsigned)cx < (unsigned)Dd && (unsigned)cy < (unsigned)Hh) {
            const float* src = w1b + (size_t)(cx * Hh + cy) * (Ww * 3) + zlo * 3;
            const uint32_t dst = sbase + t * (RS * 4) + dstob;
            asm volatile(
                "cp.async.bulk.shared::cta.global.mbarrier::complete_tx::bytes "
                "[%0], [%1], %2, [%3];"
                :: "r"(dst), "l"(src), "r"(nbytes), "r"(mbar) : "memory");
        }
    }

    // ---- Compute mapping: lane = (xsub, z16); warp task = (x-pair, y) ----
    const int xsub = lane >> 4;          // 0..1
    const int hz   = lane & 15;          // 0..15
    const int z    = z0 + hz;

    // Prefetch first task's u2 while the bulk copies are in flight.
    int task = wrp;
    int nf;
    float nux, nuy, nuz;
    {
        const int xp = task / 10, yi = task - xp * 10;
        nf  = (((b * Dd + x0 + xp * 2 + xsub) * Hh + y0 + yi) * Ww + z) * 3;
        nux = __ldg(w2 + nf + 0);
        nuy = __ldg(w2 + nf + 1);
        nuz = __ldg(w2 + nf + 2);
    }

    // Wait for tile completion (acquire).
    {
        uint32_t done;
        asm volatile(
            "{\n\t.reg .pred p;\n\t"
            "mbarrier.try_wait.parity.acquire.cta.shared::cta.b64 p, [%1], 0;\n\t"
            "selp.b32 %0, 1, 0, p;\n\t}"
            : "=r"(done) : "r"(mbar) : "memory");
        while (!done) {
            asm volatile(
                "{\n\t.reg .pred p;\n\t"
                "mbarrier.try_wait.parity.acquire.cta.shared::cta.b64 p, [%1], 0, 0x989680;\n\t"
                "selp.b32 %0, 1, 0, p;\n\t}"
                : "=r"(done) : "r"(mbar) : "memory");
        }
    }

    for (; task < NTASK; task += NWARP) {
        const int xp = task / 10;
        const int x  = x0 + xp * 2 + xsub;
        const int y  = y0 + (task - xp * 10);
        const int f  = nf;
        const float u2x = nux, u2y = nuy, u2z = nuz;

        if (task + NWARP < NTASK) {      // prefetch next task's u2
            const int nt  = task + NWARP;
            const int xp2 = nt / 10;
            nf  = (((b * Dd + x0 + xp2 * 2 + xsub) * Hh +
                    y0 + (nt - xp2 * 10)) * Ww + z) * 3;
            nux = __ldg(w2 + nf + 0);
            nuy = __ldg(w2 + nf + 1);
            nuz = __ldg(w2 + nf + 2);
        }

        const float lx = fminf(fmaxf((float)x + u2x, 0.0f), (float)(Dd - 1));
        const float ly = fminf(fmaxf((float)y + u2y, 0.0f), (float)(Hh - 1));
        const float lz = fminf(fmaxf((float)z + u2z, 0.0f), (float)(Ww - 1));

        int ix0, iy0, iz0;
        float fx, fy, fz;
        fast_floor(lx, ix0, fx);
        fast_floor(ly, iy0, fy);
        fast_floor(lz, iz0, fz);
        const float wx = lx - fx, wy = ly - fy, wz = lz - fz;
        const float wx0 = 1.0f - wx, wy0 = 1.0f - wy, wz0 = 1.0f - wz;
        // l <= 159 => i0 <= 158 => i1 = i0+1 <= 159: no clamp needed.

        const int sx0 = ix0 - (x0 - HALO);
        const int sy0 = iy0 - (y0 - HALO);
        const int sz0 = iz0 - (z0 - HALO);

        float ox, oy, oz;

        const bool fast = ((unsigned)sx0 <= (unsigned)(SX - 2)) &&
                          ((unsigned)sy0 <= (unsigned)(SY - 2)) &&
                          ((unsigned)sz0 <= (unsigned)(SZ - 2));
        if (fast) {
            const int za = sz0 * 3;
            const int zb = za + 3;

            const float* p00 = s + (sx0 * SY + sy0) * RS;
            const float* p01 = p00 + RS;                    // sy0+1
            const float* p10 = p00 + SY * RS;               // sx0+1
            const float* p11 = p10 + RS;

            float acc[3];
#pragma unroll
            for (int c = 0; c < 3; ++c) {
                const float v00 = p00[za + c] * wz0 + p00[zb + c] * wz;
                const float v01 = p01[za + c] * wz0 + p01[zb + c] * wz;
                const float v10 = p10[za + c] * wz0 + p10[zb + c] * wz;
                const float v11 = p11[za + c] * wz0 + p11[zb + c] * wz;
                acc[c] = (v00 * wy0 + v01 * wy) * wx0 +
                         (v10 * wy0 + v11 * wy) * wx;
            }
            ox = acc[0]; oy = acc[1]; oz = acc[2];
        } else {
            // Rare slow path (~0.02% of threads): direct global gather.
            const int ix1 = min(ix0 + 1, Dd - 1);
            const int iy1 = min(iy0 + 1, Hh - 1);
            const int iz1 = min(iz0 + 1, Ww - 1);
            float a0 = 0.f, a1 = 0.f, a2 = 0.f;
#pragma unroll
            for (int cx = 0; cx < 2; ++cx) {
                const int   ix  = cx ? ix1 : ix0;
                const float wxx = cx ? wx : wx0;
#pragma unroll
                for (int cy = 0; cy < 2; ++cy) {
                    const int   iy  = cy ? iy1 : iy0;
                    const float wxy = wxx * (cy ? wy : wy0);
#pragma unroll
                    for (int cz = 0; cz < 2; ++cz) {
                        const int   iz  = cz ? iz1 : iz0;
                        const float wgt = wxy * (cz ? wz : wz0);
                        const int off = ((ix * Hh + iy) * Ww + iz) * 3;
                        a0 = fmaf(__ldg(w1b + off + 0), wgt, a0);
                        a1 = fmaf(__ldg(w1b + off + 1), wgt, a1);
                        a2 = fmaf(__ldg(w1b + off + 2), wgt, a2);
                    }
                }
            }
            ox = a0; oy = a1; oz = a2;
        }

        __stcs(out + f + 0, u2x + ox);
        __stcs(out + f + 1, u2y + oy);
        __stcs(out + f + 2, u2z + oz);
    }
}

extern "C" void kernel_launch(void* const* d_in, const int* in_sizes, int n_in,
                              void* d_out, int out_size)
{
    const float* warp1 = (const float*)d_in[0];
    const float* warp2 = (const float*)d_in[1];
    float* out = (float*)d_out;

    static const size_t smem_bytes = BUF * sizeof(float) + 16;  // 93,328
    cudaFuncSetAttribute(compose_bulk_kernel,
                         cudaFuncAttributeMaxDynamicSharedMemorySize,
                         (int)smem_bytes);

    // 256 xy tiles (x-major), 10 z chunks, 2 batches = 5120 blocks.
    dim3 grid(256, Ww / TZ, 2);
    compose_bulk_kernel<<<grid, TPB, smem_bytes>>>(warp1, warp2, out);
}